// round 9
// baseline (speedup 1.0000x reference)
#include <cuda_runtime.h>
#include <cstdint>

#define HDIM 2048
#define EDIM 512
#define T_STEPS 48
#define MAXS 8

// ---------------- persistent device state (no allocations allowed) ----------
__device__ float g_x[EDIM];        // current input embedding
__device__ float g_h1[2][HDIM];    // ping-pong hidden, layer 1
__device__ float g_c1[HDIM];
__device__ float g_h2[2][HDIM];
__device__ float g_c2[HDIM];

// ---------------- threefry2x32 (JAX-compatible, 20 rounds) ------------------
__device__ __forceinline__ uint32_t rotl32(uint32_t v, int d) {
    return (v << d) | (v >> (32 - d));
}

__device__ __forceinline__ void threefry2x32(uint32_t k0, uint32_t k1,
                                             uint32_t c0, uint32_t c1,
                                             uint32_t& y0, uint32_t& y1) {
    uint32_t ks2 = k0 ^ k1 ^ 0x1BD11BDAu;
    uint32_t x0 = c0 + k0;
    uint32_t x1 = c1 + k1;
#define TF_R4(ra, rb, rc, rd)                                   \
    x0 += x1; x1 = rotl32(x1, ra); x1 ^= x0;                    \
    x0 += x1; x1 = rotl32(x1, rb); x1 ^= x0;                    \
    x0 += x1; x1 = rotl32(x1, rc); x1 ^= x0;                    \
    x0 += x1; x1 = rotl32(x1, rd); x1 ^= x0;
    TF_R4(13, 15, 26, 6);  x0 += k1;  x1 += ks2 + 1u;
    TF_R4(17, 29, 16, 24); x0 += ks2; x1 += k0 + 2u;
    TF_R4(13, 15, 26, 6);  x0 += k0;  x1 += k1 + 3u;
    TF_R4(17, 29, 16, 24); x0 += k1;  x1 += ks2 + 4u;
    TF_R4(13, 15, 26, 6);  x0 += ks2; x1 += k0 + 5u;
#undef TF_R4
    y0 = x0; y1 = x1;
}

// ---------------- init ------------------------------------------------------
__global__ void init_state_kernel() {
    int i = blockIdx.x * blockDim.x + threadIdx.x;
    if (i < EDIM) g_x[i] = 0.0f;
    if (i < HDIM) {
        g_h1[0][i] = 0.0f; g_c1[i] = 0.0f;
        g_h2[0][i] = 0.0f; g_c2[i] = 0.0f;
    }
}

// ---------------- fused LSTM cell (gates matvec + activation) ---------------
// One block = 512 threads = 16 warps = 4 h-indices x 4 gates.
// grid.x = HDIM/4 = 512 blocks.
__device__ __forceinline__ float sigf(float x) {
    return 1.0f / (1.0f + expf(-x));
}

template <int XLEN>
__global__ __launch_bounds__(512)
void lstm_cell_kernel(const float* __restrict__ Wih,
                      const float* __restrict__ Whh,
                      const float* __restrict__ bih,
                      const float* __restrict__ bhh,
                      const float* __restrict__ x,
                      const float* __restrict__ h_in,
                      float* __restrict__ h_out,
                      float* __restrict__ c) {
    __shared__ float sx[XLEN];
    __shared__ float sh[HDIM];
    __shared__ float partial[16];

    int tid = threadIdx.x;
    // stage x and h in shared (reused by all 16 warps)
    {
        const float4* x4 = (const float4*)x;
        float4* sx4 = (float4*)sx;
        for (int k = tid; k < XLEN / 4; k += 512) sx4[k] = x4[k];
        const float4* h4 = (const float4*)h_in;
        float4* sh4 = (float4*)sh;
        for (int k = tid; k < HDIM / 4; k += 512) sh4[k] = h4[k];
    }
    __syncthreads();

    int w = tid >> 5;
    int lane = tid & 31;
    int jidx = w >> 2;       // 0..3 : h-index within block
    int gate = w & 3;        // 0..3 : i,f,g,o
    int j = blockIdx.x * 4 + jidx;
    int row = gate * HDIM + j;

    float sum = 0.0f;
    {
        const float4* Wr = (const float4*)(Wih + (size_t)row * XLEN);
        const float4* sx4 = (const float4*)sx;
#pragma unroll
        for (int k = lane; k < XLEN / 4; k += 32) {
            float4 a = Wr[k]; float4 b = sx4[k];
            sum += a.x * b.x + a.y * b.y + a.z * b.z + a.w * b.w;
        }
    }
    {
        const float4* Wr = (const float4*)(Whh + (size_t)row * HDIM);
        const float4* sh4 = (const float4*)sh;
#pragma unroll
        for (int k = lane; k < HDIM / 4; k += 32) {
            float4 a = Wr[k]; float4 b = sh4[k];
            sum += a.x * b.x + a.y * b.y + a.z * b.z + a.w * b.w;
        }
    }
#pragma unroll
    for (int o = 16; o; o >>= 1) sum += __shfl_down_sync(0xffffffffu, sum, o);
    if (lane == 0) partial[w] = sum + bih[row] + bhh[row];
    __syncthreads();

    if (tid < 4) {
        int jj = blockIdx.x * 4 + tid;
        float iv = partial[tid * 4 + 0];
        float fv = partial[tid * 4 + 1];
        float gv = partial[tid * 4 + 2];
        float ov = partial[tid * 4 + 3];
        float cn = sigf(fv) * c[jj] + sigf(iv) * tanhf(gv);
        float hn = sigf(ov) * tanhf(cn);
        c[jj] = cn;
        h_out[jj] = hn;
    }
}

// ---------------- head + softmax + threefry categorical + embedding ---------
__global__ __launch_bounds__(256)
void sample_kernel(const float* __restrict__ W_out,
                   const float* __restrict__ b_out,
                   const float* __restrict__ emb,
                   const float* __restrict__ h2,
                   float* __restrict__ out,
                   int t) {
    __shared__ float sh[HDIM];
    __shared__ float slogit[MAXS];
    __shared__ int sind;

    int tid = threadIdx.x;
    {
        const float4* h4 = (const float4*)h2;
        float4* sh4 = (float4*)sh;
        for (int k = tid; k < HDIM / 4; k += 256) sh4[k] = h4[k];
    }
    __syncthreads();

    int w = tid >> 5;
    int lane = tid & 31;
    // 8 warps: warp w computes logit row w
    {
        const float4* Wr = (const float4*)(W_out + ((size_t)t * MAXS + w) * HDIM);
        const float4* sh4 = (const float4*)sh;
        float sum = 0.0f;
#pragma unroll
        for (int k = lane; k < HDIM / 4; k += 32) {
            float4 a = Wr[k]; float4 b = sh4[k];
            sum += a.x * b.x + a.y * b.y + a.z * b.z + a.w * b.w;
        }
#pragma unroll
        for (int o = 16; o; o >>= 1) sum += __shfl_down_sync(0xffffffffu, sum, o);
        if (lane == 0) slogit[w] = sum + b_out[t * MAXS + w];
    }
    __syncthreads();

    if (tid == 0) {
        const int sizes[4] = {8, 6, 4, 5};
        const int offs[4]  = {0, 8, 14, 18};
        int type = t & 3;               // t % 4
        int sz = sizes[type];
        int off = offs[type];

        float logits[MAXS];
#pragma unroll
        for (int jj = 0; jj < MAXS; jj++)
            logits[jj] = (jj < sz) ? slogit[jj] : -1e9f;

        // ---- step key: partitionable (foldlike) split of key(1)=(0,1) ----
        // child key t = threefry2x32((0,1), counter64 = t -> (hi=0, lo=t)),
        // child = (out0, out1)
        uint32_t k0, k1;
        threefry2x32(0u, 1u, 0u, (uint32_t)t, k0, k1);

        // ---- uniform bits: partitionable random_bits, 32-bit = out0 ^ out1,
        //      element l uses counter64 = l -> (hi=0, lo=l) ----
        uint32_t bits[MAXS];
#pragma unroll
        for (int l = 0; l < MAXS; l++) {
            uint32_t y0, y1;
            threefry2x32(k0, k1, 0u, (uint32_t)l, y0, y1);
            bits[l] = y0 ^ y1;
        }

        // ---- gumbel-argmax (first index wins on ties, like jnp.argmax) ----
        const float TINY = 1.17549435e-38f;
        float best = -__int_as_float(0x7f800000);  // -inf
        int bi = 0;
#pragma unroll
        for (int jj = 0; jj < MAXS; jj++) {
            uint32_t fb = (bits[jj] >> 9) | 0x3F800000u;
            float u = __uint_as_float(fb) - 1.0f;   // [0,1)
            u = fmaxf(u, TINY);
            float g = -logf(-logf(u));
            float s = logits[jj] + g;
            if (s > best) { best = s; bi = jj; }
        }

        // ---- softmax prob of chosen index ----
        float m = logits[0];
#pragma unroll
        for (int jj = 1; jj < MAXS; jj++) m = fmaxf(m, logits[jj]);
        float se = 0.0f;
#pragma unroll
        for (int jj = 0; jj < MAXS; jj++) se += expf(logits[jj] - m);
        float prob = expf(logits[bi] - m) / se;

        out[t] = (float)bi;
        out[T_STEPS + t] = prob;
        sind = off + bi;
    }
    __syncthreads();

    // next input embedding -> g_x
    {
        const float4* erow = (const float4*)(emb + (size_t)sind * EDIM);
        float4* gx4 = (float4*)g_x;
        for (int k = tid; k < EDIM / 4; k += 256) gx4[k] = erow[k];
    }
}

// ---------------- launch ----------------------------------------------------
extern "C" void kernel_launch(void* const* d_in, const int* in_sizes, int n_in,
                              void* d_out, int out_size) {
    const float* emb   = (const float*)d_in[0];
    const float* W_ih1 = (const float*)d_in[1];
    const float* W_hh1 = (const float*)d_in[2];
    const float* b_ih1 = (const float*)d_in[3];
    const float* b_hh1 = (const float*)d_in[4];
    const float* W_ih2 = (const float*)d_in[5];
    const float* W_hh2 = (const float*)d_in[6];
    const float* b_ih2 = (const float*)d_in[7];
    const float* b_hh2 = (const float*)d_in[8];
    const float* W_out = (const float*)d_in[9];
    const float* b_out = (const float*)d_in[10];
    float* out = (float*)d_out;

    float *p_x, *p_h1, *p_c1, *p_h2, *p_c2;
    cudaGetSymbolAddress((void**)&p_x,  g_x);
    cudaGetSymbolAddress((void**)&p_h1, g_h1);
    cudaGetSymbolAddress((void**)&p_c1, g_c1);
    cudaGetSymbolAddress((void**)&p_h2, g_h2);
    cudaGetSymbolAddress((void**)&p_c2, g_c2);

    init_state_kernel<<<8, 256>>>();

    for (int t = 0; t < T_STEPS; t++) {
        int in = t & 1;
        int outp = in ^ 1;
        // layer-1 cell: x(E) + h1 -> h1', c1
        lstm_cell_kernel<EDIM><<<HDIM / 4, 512>>>(
            W_ih1, W_hh1, b_ih1, b_hh1,
            p_x, p_h1 + in * HDIM, p_h1 + outp * HDIM, p_c1);
        // layer-2 cell: h1'(H) + h2 -> h2', c2
        lstm_cell_kernel<HDIM><<<HDIM / 4, 512>>>(
            W_ih2, W_hh2, b_ih2, b_hh2,
            p_h1 + outp * HDIM, p_h2 + in * HDIM, p_h2 + outp * HDIM, p_c2);
        // head + categorical sample + next embedding
        sample_kernel<<<1, 256>>>(W_out, b_out, emb, p_h2 + outp * HDIM, out, t);
    }
}

// round 17
// speedup vs baseline: 1.0617x; 1.0617x over previous
#include <cuda_runtime.h>
#include <cstdint>

#define HDIM 2048
#define EDIM 512
#define T_STEPS 48
#define MAXS 8
#define GRID 256
#define TPB 512

// ---------------- persistent device state (no allocations allowed) ----------
__device__ float g_x[EDIM];
__device__ float g_h1[2][HDIM];
__device__ float g_c1[HDIM];
__device__ float g_h2[2][HDIM];
__device__ float g_c2[HDIM];

// grid barrier state (count returns to 0 after each barrier; sense monotonic)
__device__ unsigned int g_bar_count = 0;
__device__ volatile unsigned int g_bar_sense = 0;

// ---------------- threefry2x32 (JAX partitionable, 20 rounds) ---------------
__device__ __forceinline__ uint32_t rotl32(uint32_t v, int d) {
    return (v << d) | (v >> (32 - d));
}

__device__ __forceinline__ void threefry2x32(uint32_t k0, uint32_t k1,
                                             uint32_t c0, uint32_t c1,
                                             uint32_t& y0, uint32_t& y1) {
    uint32_t ks2 = k0 ^ k1 ^ 0x1BD11BDAu;
    uint32_t x0 = c0 + k0;
    uint32_t x1 = c1 + k1;
#define TF_R4(ra, rb, rc, rd)                                   \
    x0 += x1; x1 = rotl32(x1, ra); x1 ^= x0;                    \
    x0 += x1; x1 = rotl32(x1, rb); x1 ^= x0;                    \
    x0 += x1; x1 = rotl32(x1, rc); x1 ^= x0;                    \
    x0 += x1; x1 = rotl32(x1, rd); x1 ^= x0;
    TF_R4(13, 15, 26, 6);  x0 += k1;  x1 += ks2 + 1u;
    TF_R4(17, 29, 16, 24); x0 += ks2; x1 += k0 + 2u;
    TF_R4(13, 15, 26, 6);  x0 += k0;  x1 += k1 + 3u;
    TF_R4(17, 29, 16, 24); x0 += k1;  x1 += ks2 + 4u;
    TF_R4(13, 15, 26, 6);  x0 += ks2; x1 += k0 + 5u;
#undef TF_R4
    y0 = x0; y1 = x1;
}

__device__ __forceinline__ float sigf(float x) {
    return 1.0f / (1.0f + expf(-x));
}

// ---------------- sense-reversing grid barrier ------------------------------
__device__ __forceinline__ void grid_bar() {
    __syncthreads();
    if (threadIdx.x == 0) {
        unsigned int my = g_bar_sense;          // read gen BEFORE arriving
        __threadfence();                        // release: block's writes visible
        if (atomicAdd(&g_bar_count, 1u) == GRID - 1u) {
            g_bar_count = 0u;
            __threadfence();                    // count reset before release
            g_bar_sense = my + 1u;
        } else {
            while (g_bar_sense == my) { __nanosleep(64); }
            __threadfence();                    // acquire
        }
    }
    __syncthreads();
}

// ---------------- LSTM cell phase -------------------------------------------
// Block handles 8 h-indices. 16 warps = 4 jidx x 4 gates; each warp does 2 rows.
template <int XLEN>
__device__ void cell_phase(const float* __restrict__ Wih,
                           const float* __restrict__ Whh,
                           const float* __restrict__ bih,
                           const float* __restrict__ bhh,
                           const float* __restrict__ x,
                           const float* __restrict__ h_in,
                           float* __restrict__ h_out,
                           float* __restrict__ c,
                           float* sx, float* sh, float* partial) {
    int tid = threadIdx.x;
    {
        const float4* x4 = (const float4*)x;
        float4* sx4 = (float4*)sx;
        for (int k = tid; k < XLEN / 4; k += TPB) sx4[k] = x4[k];
        const float4* h4 = (const float4*)h_in;
        float4* sh4 = (float4*)sh;
        for (int k = tid; k < HDIM / 4; k += TPB) sh4[k] = h4[k];
    }
    __syncthreads();

    int w = tid >> 5;
    int lane = tid & 31;
    int jidx = w >> 2;        // 0..3
    int gate = w & 3;         // 0..3

#pragma unroll
    for (int rep = 0; rep < 2; rep++) {
        int jloc = jidx * 2 + rep;                 // 0..7
        int j = blockIdx.x * 8 + jloc;
        int row = gate * HDIM + j;

        float sum = 0.0f;
        {
            const float4* Wr = (const float4*)(Wih + (size_t)row * XLEN);
            const float4* sx4 = (const float4*)sx;
            for (int k = lane; k < XLEN / 4; k += 32) {
                float4 a = Wr[k]; float4 b = sx4[k];
                sum += a.x * b.x + a.y * b.y + a.z * b.z + a.w * b.w;
            }
        }
        {
            const float4* Wr = (const float4*)(Whh + (size_t)row * HDIM);
            const float4* sh4 = (const float4*)sh;
            for (int k = lane; k < HDIM / 4; k += 32) {
                float4 a = Wr[k]; float4 b = sh4[k];
                sum += a.x * b.x + a.y * b.y + a.z * b.z + a.w * b.w;
            }
        }
#pragma unroll
        for (int o = 16; o; o >>= 1) sum += __shfl_down_sync(0xffffffffu, sum, o);
        if (lane == 0) partial[gate * 8 + jloc] = sum + bih[row] + bhh[row];
    }
    __syncthreads();

    if (tid < 8) {
        int jj = blockIdx.x * 8 + tid;
        float iv = partial[0 * 8 + tid];
        float fv = partial[1 * 8 + tid];
        float gv = partial[2 * 8 + tid];
        float ov = partial[3 * 8 + tid];
        float cn = sigf(fv) * c[jj] + sigf(iv) * tanhf(gv);
        float hn = sigf(ov) * tanhf(cn);
        c[jj] = cn;
        h_out[jj] = hn;
    }
    __syncthreads();
}

// ---------------- fused persistent kernel -----------------------------------
__global__ __launch_bounds__(TPB, 2)
void nas_fused_kernel(const float* __restrict__ emb,
                      const float* __restrict__ W_ih1,
                      const float* __restrict__ W_hh1,
                      const float* __restrict__ b_ih1,
                      const float* __restrict__ b_hh1,
                      const float* __restrict__ W_ih2,
                      const float* __restrict__ W_hh2,
                      const float* __restrict__ b_ih2,
                      const float* __restrict__ b_hh2,
                      const float* __restrict__ W_out,
                      const float* __restrict__ b_out,
                      float* __restrict__ out) {
    __shared__ float sx[HDIM];
    __shared__ float sh[HDIM];
    __shared__ float partial[32];
    __shared__ float slogit[MAXS];
    __shared__ int sind;

    int tid = threadIdx.x;

    // ---- init persistent state (fresh every launch / graph replay) ----
    for (int i = blockIdx.x * TPB + tid; i < EDIM; i += GRID * TPB) g_x[i] = 0.0f;
    for (int i = blockIdx.x * TPB + tid; i < HDIM; i += GRID * TPB) {
        g_h1[0][i] = 0.0f; g_h1[1][i] = 0.0f; g_c1[i] = 0.0f;
        g_h2[0][i] = 0.0f; g_h2[1][i] = 0.0f; g_c2[i] = 0.0f;
    }
    grid_bar();

    for (int t = 0; t < T_STEPS; t++) {
        int in = t & 1;
        int outp = in ^ 1;

        // ---- phase A: layer-1 cell ----
        cell_phase<EDIM>(W_ih1, W_hh1, b_ih1, b_hh1,
                         g_x, g_h1[in], g_h1[outp], g_c1, sx, sh, partial);
        grid_bar();

        // ---- phase B: layer-2 cell ----
        cell_phase<HDIM>(W_ih2, W_hh2, b_ih2, b_hh2,
                         g_h1[outp], g_h2[in], g_h2[outp], g_c2, sx, sh, partial);
        grid_bar();

        // ---- phase C: head + sample + next embedding (block 0 only) ----
        if (blockIdx.x == 0) {
            const float* h2 = g_h2[outp];
            {
                const float4* h4 = (const float4*)h2;
                float4* sh4 = (float4*)sh;
                for (int k = tid; k < HDIM / 4; k += TPB) sh4[k] = h4[k];
            }
            __syncthreads();

            int w = tid >> 5;
            int lane = tid & 31;
            if (w < MAXS) {
                const float4* Wr = (const float4*)(W_out + ((size_t)t * MAXS + w) * HDIM);
                const float4* sh4 = (const float4*)sh;
                float sum = 0.0f;
                for (int k = lane; k < HDIM / 4; k += 32) {
                    float4 a = Wr[k]; float4 b = sh4[k];
                    sum += a.x * b.x + a.y * b.y + a.z * b.z + a.w * b.w;
                }
#pragma unroll
                for (int o = 16; o; o >>= 1) sum += __shfl_down_sync(0xffffffffu, sum, o);
                if (lane == 0) slogit[w] = sum + b_out[t * MAXS + w];
            }
            __syncthreads();

            if (tid == 0) {
                const int sizes[4] = {8, 6, 4, 5};
                const int offs[4]  = {0, 8, 14, 18};
                int type = t & 3;
                int sz = sizes[type];
                int off = offs[type];

                float logits[MAXS];
#pragma unroll
                for (int jj = 0; jj < MAXS; jj++)
                    logits[jj] = (jj < sz) ? slogit[jj] : -1e9f;

                // step key: partitionable split of key(1)=(0,1)
                uint32_t k0, k1;
                threefry2x32(0u, 1u, 0u, (uint32_t)t, k0, k1);

                // uniform bits: partitionable random_bits, 32-bit = y0 ^ y1
                uint32_t bits[MAXS];
#pragma unroll
                for (int l = 0; l < MAXS; l++) {
                    uint32_t y0, y1;
                    threefry2x32(k0, k1, 0u, (uint32_t)l, y0, y1);
                    bits[l] = y0 ^ y1;
                }

                const float TINY = 1.17549435e-38f;
                float best = -__int_as_float(0x7f800000);
                int bi = 0;
#pragma unroll
                for (int jj = 0; jj < MAXS; jj++) {
                    uint32_t fb = (bits[jj] >> 9) | 0x3F800000u;
                    float u = __uint_as_float(fb) - 1.0f;
                    u = fmaxf(u, TINY);
                    float g = -logf(-logf(u));
                    float s = logits[jj] + g;
                    if (s > best) { best = s; bi = jj; }
                }

                float m = logits[0];
#pragma unroll
                for (int jj = 1; jj < MAXS; jj++) m = fmaxf(m, logits[jj]);
                float se = 0.0f;
#pragma unroll
                for (int jj = 0; jj < MAXS; jj++) se += expf(logits[jj] - m);
                float prob = expf(logits[bi] - m) / se;

                out[t] = (float)bi;
                out[T_STEPS + t] = prob;
                sind = off + bi;
            }
            __syncthreads();

            // next input embedding -> g_x
            {
                const float4* erow = (const float4*)(emb + (size_t)sind * EDIM);
                float4* gx4 = (float4*)g_x;
                for (int k = tid; k < EDIM / 4; k += TPB) gx4[k] = erow[k];
            }
        }
        grid_bar();
    }
}

// ---------------- launch ----------------------------------------------------
extern "C" void kernel_launch(void* const* d_in, const int* in_sizes, int n_in,
                              void* d_out, int out_size) {
    const float* emb   = (const float*)d_in[0];
    const float* W_ih1 = (const float*)d_in[1];
    const float* W_hh1 = (const float*)d_in[2];
    const float* b_ih1 = (const float*)d_in[3];
    const float* b_hh1 = (const float*)d_in[4];
    const float* W_ih2 = (const float*)d_in[5];
    const float* W_hh2 = (const float*)d_in[6];
    const float* b_ih2 = (const float*)d_in[7];
    const float* b_hh2 = (const float*)d_in[8];
    const float* W_out = (const float*)d_in[9];
    const float* b_out = (const float*)d_in[10];
    float* out = (float*)d_out;

    nas_fused_kernel<<<GRID, TPB>>>(emb, W_ih1, W_hh1, b_ih1, b_hh1,
                                    W_ih2, W_hh2, b_ih2, b_hh2,
                                    W_out, b_out, out);
}